// round 4
// baseline (speedup 1.0000x reference)
#include <cuda_runtime.h>
#include <math.h>

// Problem constants
#define WINDOW 40
#define E 8
#define FDIM 64
#define TDIM 64
#define KERNEL 5
#define IN_CH 144          // F + 10*E
#define LIN_IN 36          // WINDOW + 1 - KERNEL
#define NCOL 320           // WINDOW * E rank columns
#define NMAX 8192

// Scratch (device global — no allocation allowed)
__device__ float g_rankT[(size_t)NCOL * NMAX];   // [col][n]  rank/N

// ---------------------------------------------------------------------------
// Rank kernel: one block per column. 14-bit byte-packed histogram -> scan ->
// in-place key scatter (bucket-grouped) -> exact rank by tiny intra-bucket
// compare in SORTED order (warp-coherent buckets, broadcast LDS).
// Bit-exact vs argsort(argsort(-last)).
// ---------------------------------------------------------------------------
#define RT 512
#define NBIN 16384                  // 14-bit buckets of the ascending key
#define HW (NBIN / 4)               // 4096 byte-packed count words
#define CW (NBIN / 2)               // 8192 u16-packed cursor words
__device__ __forceinline__ int pphys(int w) { return w + (w >> 5); }
#define HB_PHYS (HW + HW / 32)      // 4224 words
#define CUR_PHYS (CW + CW / 32)     // 8448 words

// smem: keys u32[8192] | hb u32[HB_PHYS] | cur u32[CUR_PHYS] | order u16[8192]
#define OFF_HB   32768
#define OFF_CUR  (OFF_HB + HB_PHYS * 4)          // 49664
#define OFF_ORD  (OFF_CUR + CUR_PHYS * 4)        // 83456
#define RANK_SMEM (OFF_ORD + NMAX * 2)           // 99840 bytes -> 2 blocks/SM

__global__ __launch_bounds__(RT, 2) void rank_kernel(const float* __restrict__ x, int N) {
    extern __shared__ unsigned char sm[];
    unsigned int*   keys  = (unsigned int*)sm;             // reused as key-sorted after scatter
    unsigned int*   hb    = (unsigned int*)(sm + OFF_HB);  // byte-packed counts
    unsigned int*   cur   = (unsigned int*)(sm + OFF_CUR); // u16-packed cursors
    unsigned short* order = (unsigned short*)(sm + OFF_ORD);
    __shared__ unsigned int aux[16];

    const int c    = blockIdx.x;
    const int tid  = threadIdx.x;
    const int lane = tid & 31, wrp = tid >> 5;

    // column address: x[n, 24 + (c>>3), c&7]
    const float* colp = x + (size_t)(24 + (c >> 3)) * FDIM + (c & 7);

    for (int i = tid; i < HB_PHYS; i += RT) hb[i] = 0u;
    __syncthreads();

    // ---- load keys + byte-packed histogram (keys staged in regs for scatter) ----
    unsigned int kreg[16];
    const int npass = (N + RT - 1) / RT;   // 16 for N=8000
    #pragma unroll 4
    for (int ps = 0; ps < npass; ++ps) {
        int i = tid + ps * RT;
        unsigned int k = 0;
        if (i < N) {
            unsigned int u = __float_as_uint(__ldg(colp + (size_t)i * (TDIM * FDIM)));
            unsigned int mono = u ^ ((u >> 31) ? 0xFFFFFFFFu : 0x80000000u);
            k = ~mono;                       // ascending k == descending value
            keys[i] = k;
            unsigned int b = k >> 18;        // top 14 bits
            atomicAdd(&hb[pphys(b >> 2)], 1u << ((b & 3) * 8));
        }
        kreg[ps] = k;
    }
    __syncthreads();

    // ---- exclusive scan over 16384 bins; thread owns 8 count words = 32 bins ----
    unsigned int hv[8];
    int tsum = 0;
    #pragma unroll
    for (int w = 0; w < 8; ++w) {
        hv[w] = hb[pphys(tid * 8 + w)];
        tsum = __dp4a((int)hv[w], 0x01010101, tsum);
    }
    unsigned int v = (unsigned int)tsum;
    #pragma unroll
    for (int d = 1; d < 32; d <<= 1) {
        unsigned int t2 = __shfl_up_sync(0xFFFFFFFFu, v, d);
        if (lane >= d) v += t2;
    }
    if (lane == 31) aux[wrp] = v;
    __syncthreads();
    if (wrp == 0 && lane < 16) {
        unsigned int s = aux[lane];
        #pragma unroll
        for (int d = 1; d < 16; d <<= 1) {
            unsigned int t2 = __shfl_up_sync(0x0000FFFFu, s, d);
            if (lane >= d) s += t2;
        }
        aux[lane] = s;
    }
    __syncthreads();
    unsigned int run = v - (unsigned int)tsum + (wrp ? aux[wrp - 1] : 0u);
    // write u16-packed bucket-start cursors (2 cursor words per count word)
    #pragma unroll
    for (int w = 0; w < 8; ++w) {
        unsigned int pv = hv[w];
        unsigned int c0 = pv & 255u, c1 = (pv >> 8) & 255u, c2 = (pv >> 16) & 255u, c3 = pv >> 24;
        unsigned int s0 = run, s1 = s0 + c0, s2 = s1 + c1, s3 = s2 + c2;
        run = s3 + c3;
        cur[pphys(tid * 16 + 2 * w)]     = s0 | (s1 << 16);
        cur[pphys(tid * 16 + 2 * w + 1)] = s2 | (s3 << 16);
    }
    __syncthreads();

    // ---- scatter: keys (from regs) + indices into bucket-grouped arrays ----
    #pragma unroll 4
    for (int ps = 0; ps < npass; ++ps) {
        int i = tid + ps * RT;
        if (i < N) {
            unsigned int k = kreg[ps];
            unsigned int b = k >> 18;
            unsigned int sh = (b & 1) * 16;
            unsigned int old = atomicAdd(&cur[pphys(b >> 1)], 1u << sh);
            int pos = (old >> sh) & 0xFFFF;
            keys[pos]  = k;                    // in-place: all reads were pre-barrier
            order[pos] = (unsigned short)i;
        }
    }
    __syncthreads();
    // cursors now hold bucket ENDS.

    // ---- exact rank, processed in sorted order (warp-coherent buckets) ----
    const float inv = 1.0f / (float)N;
    float* dst = &g_rankT[(size_t)c * NMAX];
    for (int ps = 0; ps < npass; ++ps) {
        int p = tid + ps * RT;
        if (p < N) {
            unsigned int k = keys[p];
            int i = order[p];
            unsigned int b = k >> 18;
            unsigned int we = cur[pphys(b >> 1)];
            int e = (we >> ((b & 1) * 16)) & 0xFFFF;
            int s = 0;
            if (b) {
                unsigned int b1 = b - 1;
                unsigned int ws2 = cur[pphys(b1 >> 1)];
                s = (ws2 >> ((b1 & 1) * 16)) & 0xFFFF;
            }
            int r = s;
            for (int q = s; q < e; ++q) {
                unsigned int kq = keys[q];       // broadcast across warp
                if (kq < k) r++;
                else if (kq == k) r += ((int)order[q] < i);
            }
            dst[i] = (float)r * inv;
        }
    }
}

// ---------------------------------------------------------------------------
// Main kernel: per-sample stats + channel-127 conv (register-weight sliding
// accumulation) + leaky + linear. Only conv channel 127 feeds the output.
// ---------------------------------------------------------------------------
__global__ __launch_bounds__(320) void main_kernel(
    const float* __restrict__ x, const float* __restrict__ conv_w,
    const float* __restrict__ conv_b, const float* __restrict__ lin_w,
    const float* __restrict__ lin_b, float* __restrict__ out, int N)
{
    __shared__ float xe[59 * 8];          // rows 5..63 of first 8 features
    __shared__ float xc[WINDOW * IN_CH];  // assembled conv input [40][144]
    __shared__ float ws[IN_CH * KERNEL];  // conv_w[127]
    __shared__ float lw[LIN_IN];
    __shared__ float part[LIN_IN];
    __shared__ float part2[36 * 37];      // [t][chunk j], padded stride 37

    const int n   = blockIdx.x;
    const int tid = threadIdx.x;
    const float* xn = x + (size_t)n * (TDIM * FDIM);

    // ---- phase 1: loads ----
    for (int i = tid; i < IN_CH * KERNEL; i += 320) ws[i] = conv_w[127 * IN_CH * KERNEL + i];
    if (tid < LIN_IN) lw[tid] = lin_w[tid];

    for (int i = tid; i < 59 * 8; i += 320) {
        int r = i >> 3, f = i & 7;
        xe[i] = xn[(5 + r) * FDIM + f];
    }
    {   // raw channels: x[n, 24:64, 0:64] is 2560 contiguous floats
        const float4* src = (const float4*)(xn + 24 * FDIM);
        for (int q = tid; q < 640; q += 320) {
            float4 v = src[q];
            int l = q * 4;
            int t = l >> 6, i = l & 63;
            *(float4*)&xc[t * IN_CH + i] = v;
        }
    }
    {   // rank (L2-resident): same rank feeds week slot (80..87) and month (120..127)
        float r = __ldg(&g_rankT[(size_t)tid * NMAX + n]);
        int t = tid >> 3, f = tid & 7;
        xc[t * IN_CH + 80 + f]  = r;
        xc[t * IN_CH + 120 + f] = r;
    }
    __syncthreads();

    // ---- phase 2: sliding-window stats (thread = one (t,f) pair) ----
    {
        const int t = tid >> 3, f = tid & 7;
        float* row = &xc[t * IN_CH];
        float s = 0.f, s2 = 0.f, mx = -1e30f, mn = 1e30f;
        #pragma unroll
        for (int j = 0; j < 5; ++j) {
            float v = xe[(15 + t + j) * 8 + f];
            s += v; s2 = fmaf(v, v, s2);
            mx = fmaxf(mx, v); mn = fminf(mn, v);
        }
        row[64 + f] = s * 0.2f;
        row[72 + f] = sqrtf(fmaxf((s2 - s * s * 0.2f) * 0.25f, 0.f));
        row[88 + f] = mx;
        row[96 + f] = mn;
        s = 0.f; s2 = 0.f; mx = -1e30f; mn = 1e30f;
        #pragma unroll
        for (int j = 0; j < 20; ++j) {
            float v = xe[(t + j) * 8 + f];
            s += v; s2 = fmaf(v, v, s2);
            mx = fmaxf(mx, v); mn = fminf(mn, v);
        }
        row[104 + f] = s * 0.05f;
        row[112 + f] = sqrtf(fmaxf((s2 - s * s * 0.05f) * (1.0f / 19.0f), 0.f));
        row[128 + f] = mx;
        row[136 + f] = mn;
    }
    __syncthreads();

    // ---- phase 3: conv ch-127 via sliding accumulation ----
    // 144 threads: q = t-range quarter (9 outputs), j = float4 channel chunk.
    if (tid < 144) {
        const int q = tid / 36, j = tid - q * 36;
        float4 w4[KERNEL];
        #pragma unroll
        for (int k = 0; k < KERNEL; ++k) {
            w4[k].x = ws[(4 * j + 0) * KERNEL + k];
            w4[k].y = ws[(4 * j + 1) * KERNEL + k];
            w4[k].z = ws[(4 * j + 2) * KERNEL + k];
            w4[k].w = ws[(4 * j + 3) * KERNEL + k];
        }
        float acc[9];
        #pragma unroll
        for (int a = 0; a < 9; ++a) acc[a] = 0.f;
        const float4* xc4 = (const float4*)xc;
        const int r0 = 9 * q;
        #pragma unroll
        for (int rr = 0; rr < 13; ++rr) {
            float4 vv = xc4[(r0 + rr) * 36 + j];
            #pragma unroll
            for (int k = 0; k < KERNEL; ++k) {
                const int tt = rr - k;
                if (tt >= 0 && tt <= 8) {
                    acc[tt] = fmaf(w4[k].x, vv.x, acc[tt]);
                    acc[tt] = fmaf(w4[k].y, vv.y, acc[tt]);
                    acc[tt] = fmaf(w4[k].z, vv.z, acc[tt]);
                    acc[tt] = fmaf(w4[k].w, vv.w, acc[tt]);
                }
            }
        }
        #pragma unroll
        for (int a = 0; a < 9; ++a) part2[(r0 + a) * 37 + j] = acc[a];
    }
    __syncthreads();

    if (tid < LIN_IN) {
        float s = 0.f;
        #pragma unroll
        for (int j2 = 0; j2 < 36; ++j2) s += part2[tid * 37 + j2];
        s += conv_b[127];
        s = (s >= 0.0f) ? s : 0.01f * s;   // leaky ALPHA=0.01
        part[tid] = s * lw[tid];
    }
    __syncthreads();
    if (tid < 32) {
        float v = part[tid] + ((tid < 4) ? part[32 + tid] : 0.0f);
        #pragma unroll
        for (int d = 16; d > 0; d >>= 1)
            v += __shfl_down_sync(0xFFFFFFFFu, v, d);
        if (tid == 0) out[n] = v + lin_b[0];
    }
}

// ---------------------------------------------------------------------------
extern "C" void kernel_launch(void* const* d_in, const int* in_sizes, int n_in,
                              void* d_out, int out_size) {
    const float* x      = (const float*)d_in[0];
    const float* conv_w = (const float*)d_in[1];
    const float* conv_b = (const float*)d_in[2];
    const float* lin_w  = (const float*)d_in[3];
    const float* lin_b  = (const float*)d_in[4];
    float* out = (float*)d_out;
    const int N = in_sizes[0] / (TDIM * FDIM);   // 8000

    cudaFuncSetAttribute(rank_kernel, cudaFuncAttributeMaxDynamicSharedMemorySize, RANK_SMEM);

    rank_kernel<<<NCOL, RT, RANK_SMEM>>>(x, N);
    main_kernel<<<N, 320>>>(x, conv_w, conv_b, lin_w, lin_b, out, N);
}